// round 8
// baseline (speedup 1.0000x reference)
#include <cuda_runtime.h>
#include <stdint.h>

#define N_NODES   50000
#define N_EDGES   640000
#define HIDDEN    128
#define NUM_GRAPHS 50
#define EPS       1e-5f
#define STAT_NPB  64          // nodes per stats block

// Scratch (no allocations allowed)
__device__ float g_deg[N_NODES];                 // raw weighted degree
__device__ float g_stat[NUM_GRAPHS * HIDDEN];    // sum, then mu = mean*mean_scale
__device__ float g_stat2[NUM_GRAPHS * HIDDEN];   // sumsq, then A = invstd*weight
__device__ int   g_cnt[NUM_GRAPHS];
__device__ int   g_is64;                         // 1 = int64 indices, 0 = int32

__device__ __forceinline__ int load_idx(const void* p, int i, int is64, int hi)
{
    long long v = is64 ? ((const long long*)p)[i] : (long long)((const int*)p)[i];
    if (v < 0) v = 0;
    if (v > hi) v = hi;
    return (int)v;
}

__device__ __forceinline__ void red_add_v4(float* dst, float4 v)
{
    asm volatile("red.global.add.v4.f32 [%0], {%1,%2,%3,%4};"
                 :: "l"(dst), "f"(v.x), "f"(v.y), "f"(v.z), "f"(v.w) : "memory");
}

// ---------------- init: out = node (float4), zero scratch, detect dtype ----------------
__global__ void k_init(const float4* __restrict__ node, float4* __restrict__ out,
                       const int* __restrict__ ei32)
{
    if (blockIdx.x == 0) {
        int nz = 0;
        for (int k = threadIdx.x; k < 4096; k += blockDim.x)
            if (ei32[2 * k + 1] != 0) nz = 1;
        int any = __syncthreads_count(nz);
        if (threadIdx.x == 0) g_is64 = (any == 0) ? 1 : 0;
    }
    int64_t total = (int64_t)N_NODES * HIDDEN / 4;
    int64_t stride = (int64_t)gridDim.x * blockDim.x;
    for (int64_t j = (int64_t)blockIdx.x * blockDim.x + threadIdx.x; j < total; j += stride) {
        out[j] = node[j];
        if (j < N_NODES) g_deg[j] = 0.0f;
        if (j < NUM_GRAPHS * HIDDEN) { g_stat[j] = 0.0f; g_stat2[j] = 0.0f; }
        if (j < NUM_GRAPHS) g_cnt[j] = 0;
    }
}

// ---------------- degree: deg[col] += edge_attr ----------------
__global__ void k_deg(const void* __restrict__ ei, const float* __restrict__ ea)
{
    int is64 = g_is64;
    int e = blockIdx.x * blockDim.x + threadIdx.x;
    if (e < N_EDGES) {
        int c = load_idx(ei, N_EDGES + e, is64, N_NODES - 1);
        atomicAdd(&g_deg[c], ea[e]);
    }
}

// ---------------- scatter: out[col] += node[row]*w (warp/edge, v4 red, inline rsqrt) ----------------
__global__ void k_scatter(const float* __restrict__ node,
                          const void* __restrict__ ei,
                          const float* __restrict__ ea,
                          float* __restrict__ out)
{
    int is64 = g_is64;
    int lane = threadIdx.x & 31;
    int e = blockIdx.x * (blockDim.x >> 5) + (threadIdx.x >> 5);
    if (e >= N_EDGES) return;

    int r = load_idx(ei, e, is64, N_NODES - 1);
    int c = load_idx(ei, N_EDGES + e, is64, N_NODES - 1);
    float dr = g_deg[r], dc = g_deg[c];
    float ir = dr > 0.0f ? rsqrtf(dr) : 0.0f;
    float ic = dc > 0.0f ? rsqrtf(dc) : 0.0f;
    float w = ir * ea[e] * ic;

    float4 v = reinterpret_cast<const float4*>(node + (size_t)r * HIDDEN)[lane];
    v.x *= w; v.y *= w; v.z *= w; v.w *= w;
    red_add_v4(out + (size_t)c * HIDDEN + lane * 4, v);
}

// ---------------- stats helpers ----------------
__device__ __forceinline__ void stat_flush(int g, int lane, float4 s, float4 s2)
{
    float* st  = &g_stat[g * HIDDEN + lane * 4];
    float* st2 = &g_stat2[g * HIDDEN + lane * 4];
    atomicAdd(st + 0, s.x);  atomicAdd(st + 1, s.y);
    atomicAdd(st + 2, s.z);  atomicAdd(st + 3, s.w);
    atomicAdd(st2 + 0, s2.x); atomicAdd(st2 + 1, s2.y);
    atomicAdd(st2 + 2, s2.z); atomicAdd(st2 + 3, s2.w);
}

// ---------------- stats: 64 nodes/block, branch-free fast path ----------------
__global__ void k_stats(const float4* __restrict__ out,
                        const void* __restrict__ batch_ptr)
{
    int is64 = g_is64;
    int lane = threadIdx.x & 31;    // float4 channel group 0..31
    int slot = threadIdx.x >> 5;    // 0..7
    int n0 = blockIdx.x * STAT_NPB;
    int n1 = n0 + STAT_NPB;
    if (n1 > N_NODES) n1 = N_NODES;
    int cnt_nodes = n1 - n0;

    int g_first = load_idx(batch_ptr, n0, is64, NUM_GRAPHS - 1);
    int g_last  = load_idx(batch_ptr, n1 - 1, is64, NUM_GRAPHS - 1);

    float4 s  = make_float4(0.f, 0.f, 0.f, 0.f);
    float4 s2 = make_float4(0.f, 0.f, 0.f, 0.f);

    if (g_first == g_last && cnt_nodes == STAT_NPB) {
        // fast path: whole block in one graph, fully unrolled, no checks
        const float4* base = out + (size_t)n0 * 32 + lane;
        #pragma unroll
        for (int k = 0; k < STAT_NPB / 8; k++) {
            float4 v = base[(size_t)(slot + k * 8) * 32];
            s.x += v.x; s.y += v.y; s.z += v.z; s.w += v.w;
            s2.x += v.x * v.x; s2.y += v.y * v.y;
            s2.z += v.z * v.z; s2.w += v.w * v.w;
        }
        stat_flush(g_first, lane, s, s2);
        if (threadIdx.x == 0) atomicAdd(&g_cnt[g_first], cnt_nodes);
        return;
    }

    // slow path: graph boundary inside this block
    int cur_g = -1, run = 0;
    for (int n = n0 + slot; n < n1; n += 8) {
        int g = load_idx(batch_ptr, n, is64, NUM_GRAPHS - 1);
        if (g != cur_g) {
            if (cur_g >= 0) {
                stat_flush(cur_g, lane, s, s2);
                if (lane == 0) atomicAdd(&g_cnt[cur_g], run);
            }
            cur_g = g;
            s = make_float4(0.f, 0.f, 0.f, 0.f);
            s2 = make_float4(0.f, 0.f, 0.f, 0.f);
            run = 0;
        }
        float4 v = out[(size_t)n * 32 + lane];
        s.x += v.x; s.y += v.y; s.z += v.z; s.w += v.w;
        s2.x += v.x * v.x; s2.y += v.y * v.y;
        s2.z += v.z * v.z; s2.w += v.w * v.w;
        run++;
    }
    if (cur_g >= 0) {
        stat_flush(cur_g, lane, s, s2);
        if (lane == 0) atomicAdd(&g_cnt[cur_g], run);
    }
}

// ---------------- meanvar: mu = mean*ms, A = rsqrt(var+eps)*weight ----------------
__global__ void k_meanvar(const float* __restrict__ mean_scale,
                          const float* __restrict__ weight)
{
    int i = blockIdx.x * blockDim.x + threadIdx.x;
    if (i < NUM_GRAPHS * HIDDEN) {
        int g = i >> 7, ch = i & 127;
        float cnt  = fmaxf((float)g_cnt[g], 1.0f);
        float mean = g_stat[i] / cnt;
        float e2   = g_stat2[i] / cnt;
        float ms   = mean_scale[ch];
        float var  = fmaxf(e2 - mean * mean * ms * (2.0f - ms), 0.0f);
        g_stat[i]  = mean * ms;
        g_stat2[i] = rsqrtf(var + EPS) * weight[ch];
    }
}

// ---------------- final: out = relu((h - mu) * A + bias), float4 ----------------
__global__ void k_final(float4* __restrict__ out,
                        const void* __restrict__ batch_ptr,
                        const float4* __restrict__ bias4)
{
    int is64 = g_is64;
    int64_t j = (int64_t)blockIdx.x * blockDim.x + threadIdx.x;
    if (j >= (int64_t)N_NODES * (HIDDEN / 4)) return;
    const float4* mu4 = (const float4*)g_stat;
    const float4* A4  = (const float4*)g_stat2;
    int n  = (int)(j >> 5);
    int c4 = (int)(j & 31);
    int g  = load_idx(batch_ptr, n, is64, NUM_GRAPHS - 1);
    float4 h  = out[j];
    float4 mu = mu4[g * 32 + c4];
    float4 A  = A4[g * 32 + c4];
    float4 b  = bias4[c4];
    h.x = fmaxf((h.x - mu.x) * A.x + b.x, 0.0f);
    h.y = fmaxf((h.y - mu.y) * A.y + b.y, 0.0f);
    h.z = fmaxf((h.z - mu.z) * A.z + b.z, 0.0f);
    h.w = fmaxf((h.w - mu.w) * A.w + b.w, 0.0f);
    out[j] = h;
}

extern "C" void kernel_launch(void* const* d_in, const int* in_sizes, int n_in,
                              void* d_out, int out_size)
{
    // Resolve inputs by element count.
    int idx_node = -1, idx_ei = -1, idx_ea = -1, idx_bp = -1;
    int idx128[3]; int n128 = 0;
    for (int i = 0; i < n_in; i++) {
        switch (in_sizes[i]) {
            case N_NODES * HIDDEN:  idx_node = i; break;
            case 2 * N_EDGES:       idx_ei   = i; break;
            case N_EDGES:           idx_ea   = i; break;
            case N_NODES:           idx_bp   = i; break;
            case HIDDEN:            if (n128 < 3) idx128[n128++] = i; break;
        }
    }
    int idx_w, idx_b, idx_ms;
    if (idx_node >= 0 && idx_bp >= 0 && idx_node > idx_bp) {
        idx_b = idx128[0]; idx_ms = idx128[1]; idx_w = idx128[2];   // alphabetical
    } else {
        idx_w = idx128[0]; idx_b = idx128[1]; idx_ms = idx128[2];   // declaration
    }

    const float* node       = (const float*)d_in[idx_node];
    const void*  edge_index = d_in[idx_ei];
    const float* edge_attr  = (const float*)d_in[idx_ea];
    const void*  batch_ptr  = d_in[idx_bp];
    const float* weight     = (const float*)d_in[idx_w];
    const float* bias       = (const float*)d_in[idx_b];
    const float* mean_scale = (const float*)d_in[idx_ms];
    float* out = (float*)d_out;

    const int64_t NH4 = (int64_t)N_NODES * HIDDEN / 4;   // 1,600,000

    // init + dtype detect
    {
        int threads = 256;
        int blocks = (int)((NH4 + threads - 1) / threads);
        if (blocks > 8192) blocks = 8192;
        k_init<<<blocks, threads>>>((const float4*)node, (float4*)out,
                                    (const int*)edge_index);
    }
    // degree
    k_deg<<<(N_EDGES + 255) / 256, 256>>>(edge_index, edge_attr);
    // scatter: 512 threads = 16 edges per block
    k_scatter<<<(N_EDGES + 15) / 16, 512>>>(node, edge_index, edge_attr, out);
    // graphnorm
    k_stats<<<(N_NODES + STAT_NPB - 1) / STAT_NPB, 256>>>(
        (const float4*)out, batch_ptr);
    k_meanvar<<<(NUM_GRAPHS * HIDDEN + 255) / 256, 256>>>(mean_scale, weight);
    {
        int threads = 256;
        int blocks = (int)((NH4 + threads - 1) / threads);
        k_final<<<blocks, threads>>>((float4*)out, batch_ptr, (const float4*)bias);
    }
}